// round 1
// baseline (speedup 1.0000x reference)
#include <cuda_runtime.h>
#include <math.h>

#define BB 8
#define CC 19
#define NN (512*1024)
#define BN (BB*NN)
#define NB1 1024
#define NB2 4096
#define BASE1 0x3D00

// ---------------- static scratch (no allocations allowed) ----------------
__device__ float          g_prob[BN];          // 16 MB
__device__ unsigned char  g_lab[BN];           // 4 MB
__device__ int            g_hist1[BB*CC*NB1];  // 622 KB
__device__ int            g_hist2[BB*CC*NB2];  // 2.5 MB
__device__ int            g_b1[BB*CC];
__device__ int            g_r1[BB*CC];
__device__ unsigned       g_thr[BB*CC];
__device__ int            g_need[BB*CC];
__device__ int            g_claim[BB*CC];
__device__ double         g_sum;
__device__ unsigned long long g_cnt;

// ---------------- K0: zero hist1 + accumulators ----------------
__global__ void k0_init() {
    int i = blockIdx.x * blockDim.x + threadIdx.x;
    if (i < BB*CC*NB1) g_hist1[i] = 0;
    if (i == 0) { g_sum = 0.0; g_cnt = 0ull; }
}

// ---------------- K1: softmax stats + level-1 histogram ----------------
__global__ __launch_bounds__(256) void k1_stats(const float* __restrict__ pred) {
    int i = blockIdx.x * blockDim.x + threadIdx.x;   // pixel within image
    int b = blockIdx.y;
    const float* p = pred + (size_t)b * CC * NN + i;

    float v[CC];
#pragma unroll
    for (int c = 0; c < CC; c++) v[c] = p[(size_t)c * NN];

    float m = v[0]; int lab = 0;
#pragma unroll
    for (int c = 1; c < CC; c++) { if (v[c] > m) { m = v[c]; lab = c; } }

    float s = 0.0f;
#pragma unroll
    for (int c = 0; c < CC; c++) s += __expf(v[c] - m);

    float prob = __fdividef(1.0f, s);   // = max softmax prob; nll = -log(prob)

    int idx = b * NN + i;
    g_prob[idx] = prob;
    g_lab[idx]  = (unsigned char)lab;

    unsigned u = __float_as_uint(prob);
    int key1 = (int)(u >> 16) - BASE1;
    key1 = min(max(key1, 0), NB1 - 1);
    atomicAdd(&g_hist1[(b * CC + lab) * NB1 + key1], 1);
}

// ---------------- K2: level-1 select (152 blocks) + zero hist2/claim ----------------
__global__ __launch_bounds__(256) void k2_select1() {
    __shared__ int sa[NB1], sb[NB1];
    int bc = blockIdx.x;
    const int* h = &g_hist1[bc * NB1];

    for (int j = threadIdx.x; j < NB1; j += blockDim.x) sa[j] = h[j];
    // zero level-2 scratch for this class while we're here
    int* h2 = &g_hist2[bc * NB2];
    for (int j = threadIdx.x; j < NB2; j += blockDim.x) h2[j] = 0;
    if (threadIdx.x == 0) g_claim[bc] = 0;
    __syncthreads();

    // Hillis-Steele suffix sum: src[j] = sum_{t>=j} hist[t]
    int* src = sa; int* dst = sb;
    for (int d = 1; d < NB1; d <<= 1) {
        for (int j = threadIdx.x; j < NB1; j += blockDim.x)
            dst[j] = src[j] + ((j + d < NB1) ? src[j + d] : 0);
        __syncthreads();
        int* t = src; src = dst; dst = t;
    }

    int count = src[0];
    int k = (int)((float)count * 0.66f);   // matches fp32 truncation in reference

    __shared__ int s_b1;
    if (threadIdx.x == 0) s_b1 = -1;
    __syncthreads();
    if (k > 0) {
        for (int j = threadIdx.x; j < NB1; j += blockDim.x) {
            int sj  = src[j];
            int sj1 = (j + 1 < NB1) ? src[j + 1] : 0;
            if (sj >= k && sj1 < k) s_b1 = j;   // unique crossing
        }
    }
    __syncthreads();
    if (threadIdx.x == 0) {
        int b1 = s_b1;
        g_b1[bc] = b1;
        g_r1[bc] = (b1 >= 0) ? (k - ((b1 + 1 < NB1) ? src[b1 + 1] : 0)) : 0;
    }
}

// ---------------- K3: level-2 histogram (pixels in crossing bucket only) ----------------
__global__ __launch_bounds__(256) void k3_hist2() {
    int i = blockIdx.x * blockDim.x + threadIdx.x;
    int b = blockIdx.y;
    int idx = b * NN + i;
    unsigned u = __float_as_uint(g_prob[idx]);
    int lab = g_lab[idx];
    int bc = b * CC + lab;
    int key1 = (int)(u >> 16) - BASE1;
    key1 = min(max(key1, 0), NB1 - 1);
    if (key1 == g_b1[bc]) {
        int key2 = (u >> 4) & 0xFFF;
        atomicAdd(&g_hist2[bc * NB2 + key2], 1);
    }
}

// ---------------- K4: level-2 select -> exact 28-bit threshold ----------------
__global__ __launch_bounds__(256) void k4_select2() {
    __shared__ int sa[NB2], sb[NB2];
    int bc = blockIdx.x;
    int b1 = g_b1[bc];
    if (b1 < 0) {
        if (threadIdx.x == 0) { g_thr[bc] = 0xFFFFFFFFu; g_need[bc] = 0; }
        return;
    }
    int r = g_r1[bc];
    const int* h = &g_hist2[bc * NB2];
    for (int j = threadIdx.x; j < NB2; j += blockDim.x) sa[j] = h[j];
    __syncthreads();

    int* src = sa; int* dst = sb;
    for (int d = 1; d < NB2; d <<= 1) {
        for (int j = threadIdx.x; j < NB2; j += blockDim.x)
            dst[j] = src[j] + ((j + d < NB2) ? src[j + d] : 0);
        __syncthreads();
        int* t = src; src = dst; dst = t;
    }

    __shared__ int s_t2;
    if (threadIdx.x == 0) s_t2 = NB2 - 1;
    __syncthreads();
    for (int j = threadIdx.x; j < NB2; j += blockDim.x) {
        int sj  = src[j];
        int sj1 = (j + 1 < NB2) ? src[j + 1] : 0;
        if (sj >= r && sj1 < r) s_t2 = j;
    }
    __syncthreads();
    if (threadIdx.x == 0) {
        int t2 = s_t2;
        int above = (t2 + 1 < NB2) ? src[t2 + 1] : 0;
        g_need[bc] = r - above;
        g_thr[bc] = (((unsigned)(BASE1 + b1)) << 16) | ((unsigned)t2 << 4) | 0xFu;
    }
}

// ---------------- K5: selection + reduction ----------------
__global__ __launch_bounds__(256) void k5_reduce() {
    int i = blockIdx.x * blockDim.x + threadIdx.x;
    int b = blockIdx.y;
    int idx = b * NN + i;
    float prob = g_prob[idx];
    int lab = g_lab[idx];
    int bc = b * CC + lab;
    unsigned u = __float_as_uint(prob);

    bool sel = (prob > 0.9f);
    if (!sel) {
        unsigned thr = g_thr[bc];
        if (u > thr) sel = true;
        else if ((u | 0xFu) == thr)
            sel = (atomicAdd(&g_claim[bc], 1) < g_need[bc]);
    }

    float nll = sel ? -__logf(prob) : 0.0f;
    int   cnt = sel ? 1 : 0;

#pragma unroll
    for (int o = 16; o > 0; o >>= 1) {
        nll += __shfl_xor_sync(0xFFFFFFFFu, nll, o);
        cnt += __shfl_xor_sync(0xFFFFFFFFu, cnt, o);
    }
    __shared__ float ws[8];
    __shared__ int   wc[8];
    int wid = threadIdx.x >> 5, lid = threadIdx.x & 31;
    if (lid == 0) { ws[wid] = nll; wc[wid] = cnt; }
    __syncthreads();
    if (threadIdx.x == 0) {
        float s = 0.0f; int c = 0;
#pragma unroll
        for (int w = 0; w < 8; w++) { s += ws[w]; c += wc[w]; }
        if (c > 0) {
            atomicAdd(&g_sum, (double)s);
            atomicAdd(&g_cnt, (unsigned long long)c);
        }
    }
}

// ---------------- K6: finalize ----------------
__global__ void k6_final(float* out) {
    unsigned long long c = g_cnt;
    if (c == 0) c = 1;
    out[0] = (float)(g_sum / (double)c);
}

// ---------------- launch ----------------
extern "C" void kernel_launch(void* const* d_in, const int* in_sizes, int n_in,
                              void* d_out, int out_size) {
    const float* pred = (const float*)d_in[0];
    float* out = (float*)d_out;

    {
        int tot = BB * CC * NB1;
        k0_init<<<(tot + 255) / 256, 256>>>();
    }
    {
        dim3 grid(NN / 256, BB);
        k1_stats<<<grid, 256>>>(pred);
    }
    k2_select1<<<BB * CC, 256>>>();
    {
        dim3 grid(NN / 256, BB);
        k3_hist2<<<grid, 256>>>();
    }
    k4_select2<<<BB * CC, 256>>>();
    {
        dim3 grid(NN / 256, BB);
        k5_reduce<<<grid, 256>>>();
    }
    k6_final<<<1, 1>>>(out);
}

// round 2
// speedup vs baseline: 1.2518x; 1.2518x over previous
#include <cuda_runtime.h>
#include <math.h>

#define BB 8
#define CC 19
#define NN (512*1024)
#define BN (BB*NN)
#define NB1 1024
#define NB2 4096
#define BASE1 0x3D00

// ---------------- static scratch ----------------
__device__ unsigned       g_key[BN];           // 16 MB: (prob_bits & ~31) | lab
__device__ int            g_hist1[BB*CC*NB1];  // 622 KB
__device__ int            g_hist2[BB*CC*NB2];  // 2.5 MB
__device__ int            g_b1[BB*CC];
__device__ int            g_r1[BB*CC];
__device__ unsigned       g_thrs[BB*CC];       // threshold prefix (bits>>5)
__device__ int            g_need[BB*CC];
__device__ int            g_claim[BB*CC];
__device__ double         g_sum;
__device__ unsigned long long g_cnt;

// ---------------- K0: zero hist1 + accumulators ----------------
__global__ void k0_init() {
    int i = blockIdx.x * blockDim.x + threadIdx.x;
    if (i < BB*CC*NB1) g_hist1[i] = 0;
    if (i == 0) { g_sum = 0.0; g_cnt = 0ull; }
}

// ---------------- K1: online softmax stats (x4 vectorized) + level-1 hist ----------------
__global__ __launch_bounds__(256) void k1_stats(const float* __restrict__ pred) {
    int t = blockIdx.x * blockDim.x + threadIdx.x;   // float4 index within image
    int b = blockIdx.y;
    const float4* p = (const float4*)(pred + (size_t)b * CC * NN) + t;
    const int cs = NN / 4;   // class stride in float4 units

    float4 v = p[0];
    float m[4] = { v.x, v.y, v.z, v.w };
    float s[4] = { 1.0f, 1.0f, 1.0f, 1.0f };
    int   lb[4] = { 0, 0, 0, 0 };

#pragma unroll
    for (int c = 1; c < CC; c++) {
        float4 w = p[c * cs];
        float vv[4] = { w.x, w.y, w.z, w.w };
#pragma unroll
        for (int j = 0; j < 4; j++) {
            float x = vv[j];
            if (x > m[j]) {
                s[j] = s[j] * __expf(m[j] - x) + 1.0f;
                m[j] = x; lb[j] = c;
            } else {
                s[j] += __expf(x - m[j]);
            }
        }
    }

    uint4 out;
    unsigned uo[4];
#pragma unroll
    for (int j = 0; j < 4; j++) {
        float prob = __fdividef(1.0f, s[j]);
        unsigned u = __float_as_uint(prob);
        uo[j] = (u & ~31u) | (unsigned)lb[j];
        int key1 = (int)(u >> 16) - BASE1;
        key1 = min(max(key1, 0), NB1 - 1);
        atomicAdd(&g_hist1[(b * CC + lb[j]) * NB1 + key1], 1);
    }
    out.x = uo[0]; out.y = uo[1]; out.z = uo[2]; out.w = uo[3];
    ((uint4*)g_key)[b * cs + t] = out;
}

// ---------------- K2: level-1 select (152 blocks) + zero hist2/claim ----------------
__global__ __launch_bounds__(256) void k2_select1() {
    __shared__ int sa[NB1], sb[NB1];
    int bc = blockIdx.x;
    const int* h = &g_hist1[bc * NB1];

    for (int j = threadIdx.x; j < NB1; j += blockDim.x) sa[j] = h[j];
    int* h2 = &g_hist2[bc * NB2];
    for (int j = threadIdx.x; j < NB2; j += blockDim.x) h2[j] = 0;
    if (threadIdx.x == 0) g_claim[bc] = 0;
    __syncthreads();

    int* src = sa; int* dst = sb;
    for (int d = 1; d < NB1; d <<= 1) {
        for (int j = threadIdx.x; j < NB1; j += blockDim.x)
            dst[j] = src[j] + ((j + d < NB1) ? src[j + d] : 0);
        __syncthreads();
        int* tp = src; src = dst; dst = tp;
    }

    int count = src[0];
    int k = (int)((float)count * 0.66f);   // fp32 truncation, matches reference

    __shared__ int s_b1;
    if (threadIdx.x == 0) s_b1 = -1;
    __syncthreads();
    if (k > 0) {
        for (int j = threadIdx.x; j < NB1; j += blockDim.x) {
            int sj  = src[j];
            int sj1 = (j + 1 < NB1) ? src[j + 1] : 0;
            if (sj >= k && sj1 < k) s_b1 = j;
        }
    }
    __syncthreads();
    if (threadIdx.x == 0) {
        int b1 = s_b1;
        g_b1[bc] = b1;
        g_r1[bc] = (b1 >= 0) ? (k - ((b1 + 1 < NB1) ? src[b1 + 1] : 0)) : 0;
    }
}

// ---------------- K3: level-2 histogram (x4 vectorized) ----------------
__global__ __launch_bounds__(256) void k3_hist2() {
    __shared__ int sb1[CC];
    int b = blockIdx.y;
    if (threadIdx.x < CC) sb1[threadIdx.x] = g_b1[b * CC + threadIdx.x];
    __syncthreads();

    int t = blockIdx.x * blockDim.x + threadIdx.x;
    uint4 kk = ((const uint4*)g_key)[b * (NN/4) + t];
    unsigned u[4] = { kk.x, kk.y, kk.z, kk.w };
#pragma unroll
    for (int j = 0; j < 4; j++) {
        int lab = (int)(u[j] & 31u);
        int key1 = (int)(u[j] >> 16) - BASE1;
        if (key1 == sb1[lab]) {
            int bc = b * CC + lab;
            atomicAdd(&g_hist2[bc * NB2 + ((u[j] >> 5) & 0xFFFu)], 1);
        }
    }
}

// ---------------- K4: level-2 select -> 27-bit threshold prefix ----------------
__global__ __launch_bounds__(256) void k4_select2() {
    __shared__ int sa[NB2], sb[NB2];
    int bc = blockIdx.x;
    int b1 = g_b1[bc];
    if (b1 < 0) {
        if (threadIdx.x == 0) { g_thrs[bc] = 0xFFFFFFFFu; g_need[bc] = 0; }
        return;
    }
    int r = g_r1[bc];
    const int* h = &g_hist2[bc * NB2];
    for (int j = threadIdx.x; j < NB2; j += blockDim.x) sa[j] = h[j];
    __syncthreads();

    int* src = sa; int* dst = sb;
    for (int d = 1; d < NB2; d <<= 1) {
        for (int j = threadIdx.x; j < NB2; j += blockDim.x)
            dst[j] = src[j] + ((j + d < NB2) ? src[j + d] : 0);
        __syncthreads();
        int* tp = src; src = dst; dst = tp;
    }

    __shared__ int s_t2;
    if (threadIdx.x == 0) s_t2 = NB2 - 1;
    __syncthreads();
    for (int j = threadIdx.x; j < NB2; j += blockDim.x) {
        int sj  = src[j];
        int sj1 = (j + 1 < NB2) ? src[j + 1] : 0;
        if (sj >= r && sj1 < r) s_t2 = j;
    }
    __syncthreads();
    if (threadIdx.x == 0) {
        int t2 = s_t2;
        int above = (t2 + 1 < NB2) ? src[t2 + 1] : 0;
        g_need[bc] = r - above;
        // pixel prefix = key>>5 (bits 5..31); threshold prefix:
        g_thrs[bc] = (((unsigned)(BASE1 + b1)) << 11) | (unsigned)t2;
    }
}

// ---------------- K5: selection + reduction (x4 vectorized) ----------------
__global__ __launch_bounds__(256) void k5_reduce() {
    __shared__ unsigned sthr[CC];
    int b = blockIdx.y;
    if (threadIdx.x < CC) sthr[threadIdx.x] = g_thrs[b * CC + threadIdx.x];
    __syncthreads();

    int t = blockIdx.x * blockDim.x + threadIdx.x;
    uint4 kk = ((const uint4*)g_key)[b * (NN/4) + t];
    unsigned u[4] = { kk.x, kk.y, kk.z, kk.w };

    float nll = 0.0f;
    int   cnt = 0;
#pragma unroll
    for (int j = 0; j < 4; j++) {
        int lab = (int)(u[j] & 31u);
        float prob = __uint_as_float(u[j] & ~31u);
        unsigned ph = u[j] >> 5;
        unsigned thr = sthr[lab];
        bool sel = (prob > 0.9f) || (ph > thr);
        if (!sel && ph == thr) {
            int bc = b * CC + lab;
            sel = (atomicAdd(&g_claim[bc], 1) < g_need[bc]);
        }
        if (sel) { nll += -__logf(prob); cnt++; }
    }

#pragma unroll
    for (int o = 16; o > 0; o >>= 1) {
        nll += __shfl_xor_sync(0xFFFFFFFFu, nll, o);
        cnt += __shfl_xor_sync(0xFFFFFFFFu, cnt, o);
    }
    __shared__ float ws[8];
    __shared__ int   wc[8];
    int wid = threadIdx.x >> 5, lid = threadIdx.x & 31;
    if (lid == 0) { ws[wid] = nll; wc[wid] = cnt; }
    __syncthreads();
    if (threadIdx.x == 0) {
        float s = 0.0f; int c = 0;
#pragma unroll
        for (int w = 0; w < 8; w++) { s += ws[w]; c += wc[w]; }
        if (c > 0) {
            atomicAdd(&g_sum, (double)s);
            atomicAdd(&g_cnt, (unsigned long long)c);
        }
    }
}

// ---------------- K6: finalize ----------------
__global__ void k6_final(float* out) {
    unsigned long long c = g_cnt;
    if (c == 0) c = 1;
    out[0] = (float)(g_sum / (double)c);
}

// ---------------- launch ----------------
extern "C" void kernel_launch(void* const* d_in, const int* in_sizes, int n_in,
                              void* d_out, int out_size) {
    const float* pred = (const float*)d_in[0];
    float* out = (float*)d_out;

    {
        int tot = BB * CC * NB1;
        k0_init<<<(tot + 255) / 256, 256>>>();
    }
    {
        dim3 grid(NN / (256 * 4), BB);   // 512 x 8
        k1_stats<<<grid, 256>>>(pred);
    }
    k2_select1<<<BB * CC, 256>>>();
    {
        dim3 grid(NN / (256 * 4), BB);
        k3_hist2<<<grid, 256>>>();
    }
    k4_select2<<<BB * CC, 256>>>();
    {
        dim3 grid(NN / (256 * 4), BB);
        k5_reduce<<<grid, 256>>>();
    }
    k6_final<<<1, 1>>>(out);
}

// round 3
// speedup vs baseline: 2.1895x; 1.7491x over previous
#include <cuda_runtime.h>
#include <math.h>

#define BB 8
#define CC 19
#define NN (512*1024)
#define BN (BB*NN)
#define NB12 10752            // 20-bit prefix buckets: (u>>12) - BASE12
#define BASE12 0x3D000        // prefix of prob = 1/19 lower bound
#define CH12 (NB12/256)       // 42 buckets per thread in k2

// ---------------- static scratch ----------------
__device__ __align__(16) unsigned g_key[BN];            // 16 MB: (prob_bits & ~31) | lab
__device__ __align__(16) int      g_hist1[BB*CC*NB12];  // 6.5 MB
__device__ unsigned       g_thr[BB*CC];    // absolute 20-bit threshold prefix
__device__ int            g_need[BB*CC];
__device__ int            g_claim[BB*CC];
__device__ double         g_sum;
__device__ unsigned long long g_cnt;

// ---------------- K0: zero hist + claim + accumulators ----------------
__global__ void k0_init() {
    int i = blockIdx.x * blockDim.x + threadIdx.x;
    int4 z = make_int4(0, 0, 0, 0);
    if (i < BB*CC*NB12/4) ((int4*)g_hist1)[i] = z;
    if (i < BB*CC) g_claim[i] = 0;
    if (i == 0) { g_sum = 0.0; g_cnt = 0ull; }
}

// ---------------- K1: softmax stats (register-buffered x4) + 20-bit hist ----------------
__global__ __launch_bounds__(256) void k1_stats(const float* __restrict__ pred) {
    int t = blockIdx.x * blockDim.x + threadIdx.x;   // float4 index within image
    int b = blockIdx.y;
    const float4* p = (const float4*)(pred + (size_t)b * CC * NN) + t;
    const int cs = NN / 4;

    // front-batch all 19 loads -> MLP=19
    float4 r[CC];
#pragma unroll
    for (int c = 0; c < CC; c++) r[c] = p[c * cs];

    unsigned uo[4];
#define PROC(J, FIELD) { \
    float m = r[0].FIELD; int lab = 0; \
    _Pragma("unroll") \
    for (int c = 1; c < CC; c++) { float x = r[c].FIELD; if (x > m) { m = x; lab = c; } } \
    float s = 0.0f; \
    _Pragma("unroll") \
    for (int c = 0; c < CC; c++) s += __expf(r[c].FIELD - m); \
    float prob = __fdividef(1.0f, s); \
    unsigned u = __float_as_uint(prob); \
    uo[J] = (u & ~31u) | (unsigned)lab; \
    int key1 = min((int)(u >> 12) - BASE12, NB12 - 1); \
    key1 = max(key1, 0); \
    atomicAdd(&g_hist1[(b * CC + lab) * NB12 + key1], 1); }

    PROC(0, x) PROC(1, y) PROC(2, z) PROC(3, w)
#undef PROC

    uint4 out; out.x = uo[0]; out.y = uo[1]; out.z = uo[2]; out.w = uo[3];
    ((uint4*)g_key)[b * cs + t] = out;
}

// ---------------- K2: per-(image,class) threshold select (152 blocks) ----------------
__global__ __launch_bounds__(256) void k2_select1() {
    int bc = blockIdx.x;
    const int* h = &g_hist1[bc * NB12];
    int t0 = threadIdx.x * CH12;

    // chunk sum
    int s = 0;
#pragma unroll 6
    for (int j = 0; j < CH12; j++) s += h[t0 + j];

    // block-wide inclusive suffix scan of chunk sums
    __shared__ int sa[256], sb[256];
    sa[threadIdx.x] = s;
    __syncthreads();
    int* src = sa; int* dst = sb;
    for (int d = 1; d < 256; d <<= 1) {
        int v = src[threadIdx.x] + ((threadIdx.x + d < 256) ? src[threadIdx.x + d] : 0);
        dst[threadIdx.x] = v;
        __syncthreads();
        int* tp = src; src = dst; dst = tp;
    }

    int total = src[0];
    int k = (int)((float)total * 0.66f);   // fp32 truncation matches reference
    int above = (threadIdx.x + 1 < 256) ? src[threadIdx.x + 1] : 0;

    __shared__ int s_b1, s_need;
    if (threadIdx.x == 0) { s_b1 = -1; s_need = 0; }
    __syncthreads();

    if (k > 0 && above < k && above + s >= k) {
        // crossing lies in my chunk; walk high->low (high bucket = high prob)
        int cum = above;
        for (int j = CH12 - 1; j >= 0; j--) {
            int hj = h[t0 + j];
            if (cum < k && cum + hj >= k) { s_b1 = t0 + j; s_need = k - cum; }
            cum += hj;
        }
    }
    __syncthreads();
    if (threadIdx.x == 0) {
        g_thr[bc]  = (s_b1 >= 0) ? (unsigned)(BASE12 + s_b1) : 0xFFFFFFFFu;
        g_need[bc] = s_need;
    }
}

// ---------------- K5: selection + reduction (2x uint4 per thread) ----------------
__global__ __launch_bounds__(256) void k5_reduce() {
    __shared__ unsigned sthr[CC];
    int b = blockIdx.y;
    if (threadIdx.x < CC) sthr[threadIdx.x] = g_thr[b * CC + threadIdx.x];
    __syncthreads();

    int t = blockIdx.x * blockDim.x + threadIdx.x;
    const uint4* kp = (const uint4*)g_key + b * (NN / 4);
    const int half = NN / 8;   // uint4 elements per half
    uint4 v0 = kp[t];
    uint4 v1 = kp[t + half];
    unsigned u[8] = { v0.x, v0.y, v0.z, v0.w, v1.x, v1.y, v1.z, v1.w };

    float nll = 0.0f;
    int   cnt = 0;
#pragma unroll
    for (int j = 0; j < 8; j++) {
        int lab = (int)(u[j] & 31u);
        float prob = __uint_as_float(u[j] & ~31u);
        unsigned ph = u[j] >> 12;
        unsigned thr = sthr[lab];
        bool sel = (prob > 0.9f) || (ph > thr);
        if (!sel && ph == thr) {
            int bc = b * CC + lab;
            sel = (atomicAdd(&g_claim[bc], 1) < g_need[bc]);
        }
        if (sel) { nll += -__logf(prob); cnt++; }
    }

#pragma unroll
    for (int o = 16; o > 0; o >>= 1) {
        nll += __shfl_xor_sync(0xFFFFFFFFu, nll, o);
        cnt += __shfl_xor_sync(0xFFFFFFFFu, cnt, o);
    }
    __shared__ float ws[8];
    __shared__ int   wc[8];
    int wid = threadIdx.x >> 5, lid = threadIdx.x & 31;
    if (lid == 0) { ws[wid] = nll; wc[wid] = cnt; }
    __syncthreads();
    if (threadIdx.x == 0) {
        float s = 0.0f; int c = 0;
#pragma unroll
        for (int w = 0; w < 8; w++) { s += ws[w]; c += wc[w]; }
        if (c > 0) {
            atomicAdd(&g_sum, (double)s);
            atomicAdd(&g_cnt, (unsigned long long)c);
        }
    }
}

// ---------------- K6: finalize ----------------
__global__ void k6_final(float* out) {
    unsigned long long c = g_cnt;
    if (c == 0) c = 1;
    out[0] = (float)(g_sum / (double)c);
}

// ---------------- launch ----------------
extern "C" void kernel_launch(void* const* d_in, const int* in_sizes, int n_in,
                              void* d_out, int out_size) {
    const float* pred = (const float*)d_in[0];
    float* out = (float*)d_out;

    {
        int tot = BB * CC * NB12 / 4;
        k0_init<<<(tot + 255) / 256, 256>>>();
    }
    {
        dim3 grid(NN / (256 * 4), BB);   // 512 x 8
        k1_stats<<<grid, 256>>>(pred);
    }
    k2_select1<<<BB * CC, 256>>>();
    {
        dim3 grid(NN / (256 * 8), BB);   // 256 x 8
        k5_reduce<<<grid, 256>>>();
    }
    k6_final<<<1, 1>>>(out);
}

// round 4
// speedup vs baseline: 2.2453x; 1.0255x over previous
#include <cuda_runtime.h>
#include <math.h>

#define BB 8
#define CC 19
#define NN (512*1024)
#define BN (BB*NN)
#define NB12 10752            // 20-bit prefix buckets: (u>>12) - BASE12
#define BASE12 0x3D000
#define CH12 (NB12/256)       // 42 buckets per thread in k2
#define K5_BLOCKS (NN/(256*16)*BB)   // 128 x 8 = 1024

// ---------------- static scratch (zero-initialized at module load; every
// kernel leaves its state zeroed for the next graph replay) ----------------
__device__ __align__(16) unsigned g_key[BN];            // 16 MB
__device__ __align__(16) int      g_hist1[BB*CC*NB12];  // 6.5 MB
__device__ unsigned       g_thr[BB*CC];
__device__ int            g_need[BB*CC];
__device__ int            g_claim[BB*CC];
__device__ double         g_sum;
__device__ unsigned long long g_cnt;
__device__ unsigned       g_done;

// ---------------- K1: softmax stats (register-buffered x4, streaming loads)
//                  + 20-bit per-(image,class) histogram ----------------
__global__ __launch_bounds__(256) void k1_stats(const float* __restrict__ pred) {
    int t = blockIdx.x * blockDim.x + threadIdx.x;   // float4 index within image
    int b = blockIdx.y;
    const float4* p = (const float4*)(pred + (size_t)b * CC * NN) + t;
    const int cs = NN / 4;

    // front-batch all 19 loads (MLP=19); evict-first so g_key stays in L2
    float4 r[CC];
#pragma unroll
    for (int c = 0; c < CC; c++) r[c] = __ldcs(&p[c * cs]);

    unsigned uo[4];
#define PROC(J, FIELD) { \
    float m = r[0].FIELD; int lab = 0; \
    _Pragma("unroll") \
    for (int c = 1; c < CC; c++) { float x = r[c].FIELD; if (x > m) { m = x; lab = c; } } \
    float s = 0.0f; \
    _Pragma("unroll") \
    for (int c = 0; c < CC; c++) s += __expf(r[c].FIELD - m); \
    float prob = __fdividef(1.0f, s); \
    unsigned u = __float_as_uint(prob); \
    uo[J] = (u & ~31u) | (unsigned)lab; \
    int key1 = min((int)(u >> 12) - BASE12, NB12 - 1); \
    key1 = max(key1, 0); \
    atomicAdd(&g_hist1[(b * CC + lab) * NB12 + key1], 1); }

    PROC(0, x) PROC(1, y) PROC(2, z) PROC(3, w)
#undef PROC

    uint4 out; out.x = uo[0]; out.y = uo[1]; out.z = uo[2]; out.w = uo[3];
    ((uint4*)g_key)[b * cs + t] = out;
}

// ---------------- K2: per-(image,class) threshold select (152 blocks);
//                  re-zeroes its histogram slice after reading ----------------
__global__ __launch_bounds__(256) void k2_select1() {
    int bc = blockIdx.x;
    int* h = &g_hist1[bc * NB12];
    int t0 = threadIdx.x * CH12;

    // chunk values -> registers, then zero global copy for next replay
    int hv[CH12];
    int s = 0;
#pragma unroll 6
    for (int j = 0; j < CH12; j++) { hv[j] = h[t0 + j]; s += hv[j]; }
#pragma unroll 6
    for (int j = 0; j < CH12; j++) h[t0 + j] = 0;

    // block-wide inclusive suffix scan of chunk sums
    __shared__ int sa[256], sb[256];
    sa[threadIdx.x] = s;
    __syncthreads();
    int* src = sa; int* dst = sb;
    for (int d = 1; d < 256; d <<= 1) {
        int v = src[threadIdx.x] + ((threadIdx.x + d < 256) ? src[threadIdx.x + d] : 0);
        dst[threadIdx.x] = v;
        __syncthreads();
        int* tp = src; src = dst; dst = tp;
    }

    int total = src[0];
    int k = (int)((float)total * 0.66f);   // fp32 truncation matches reference
    int above = (threadIdx.x + 1 < 256) ? src[threadIdx.x + 1] : 0;

    __shared__ int s_b1, s_need;
    if (threadIdx.x == 0) { s_b1 = -1; s_need = 0; }
    __syncthreads();

    if (k > 0 && above < k && above + s >= k) {
        int cum = above;
        for (int j = CH12 - 1; j >= 0; j--) {
            int hj = hv[j];
            if (cum < k && cum + hj >= k) { s_b1 = t0 + j; s_need = k - cum; }
            cum += hj;
        }
    }
    __syncthreads();
    if (threadIdx.x == 0) {
        g_thr[bc]  = (s_b1 >= 0) ? (unsigned)(BASE12 + s_b1) : 0xFFFFFFFFu;
        g_need[bc] = s_need;
    }
}

// ---------------- K5: selection + reduction (4x uint4 per thread) + fused
//                  finalize via last-block ticket; resets accumulators ----------------
__global__ __launch_bounds__(256) void k5_reduce(float* __restrict__ out) {
    __shared__ unsigned sthr[CC];
    int b = blockIdx.y;
    if (threadIdx.x < CC) sthr[threadIdx.x] = g_thr[b * CC + threadIdx.x];
    __syncthreads();

    int t = blockIdx.x * blockDim.x + threadIdx.x;
    const uint4* kp = (const uint4*)g_key + b * (NN / 4);
    const int q = NN / 16;   // quarter, in uint4 units
    uint4 v0 = kp[t];
    uint4 v1 = kp[t + q];
    uint4 v2 = kp[t + 2 * q];
    uint4 v3 = kp[t + 3 * q];
    unsigned u[16] = { v0.x, v0.y, v0.z, v0.w, v1.x, v1.y, v1.z, v1.w,
                       v2.x, v2.y, v2.z, v2.w, v3.x, v3.y, v3.z, v3.w };

    float nll = 0.0f;
    int   cnt = 0;
#pragma unroll
    for (int j = 0; j < 16; j++) {
        int lab = (int)(u[j] & 31u);
        float prob = __uint_as_float(u[j] & ~31u);
        unsigned ph = u[j] >> 12;
        unsigned thr = sthr[lab];
        bool sel = (prob > 0.9f) || (ph > thr);
        if (!sel && ph == thr) {
            int bc = b * CC + lab;
            sel = (atomicAdd(&g_claim[bc], 1) < g_need[bc]);
        }
        if (sel) { nll += -__logf(prob); cnt++; }
    }

#pragma unroll
    for (int o = 16; o > 0; o >>= 1) {
        nll += __shfl_xor_sync(0xFFFFFFFFu, nll, o);
        cnt += __shfl_xor_sync(0xFFFFFFFFu, cnt, o);
    }
    __shared__ float ws[8];
    __shared__ int   wc[8];
    int wid = threadIdx.x >> 5, lid = threadIdx.x & 31;
    if (lid == 0) { ws[wid] = nll; wc[wid] = cnt; }
    __syncthreads();
    if (threadIdx.x == 0) {
        float s = 0.0f; int c = 0;
#pragma unroll
        for (int w = 0; w < 8; w++) { s += ws[w]; c += wc[w]; }
        if (c > 0) {
            atomicAdd(&g_sum, (double)s);
            atomicAdd(&g_cnt, (unsigned long long)c);
        }
        __threadfence();
        unsigned ticket = atomicAdd(&g_done, 1);
        if (ticket == K5_BLOCKS - 1) {
            // last block: finalize + reset all cross-replay state
            double            fs = atomicAdd(&g_sum, 0.0);
            unsigned long long fc = atomicAdd(&g_cnt, 0ull);
            if (fc == 0) fc = 1;
            out[0] = (float)(fs / (double)fc);
            g_sum = 0.0; g_cnt = 0ull; g_done = 0u;
            for (int i = 0; i < BB * CC; i++) g_claim[i] = 0;
        }
    }
}

// ---------------- launch ----------------
extern "C" void kernel_launch(void* const* d_in, const int* in_sizes, int n_in,
                              void* d_out, int out_size) {
    const float* pred = (const float*)d_in[0];
    float* out = (float*)d_out;

    {
        dim3 grid(NN / (256 * 4), BB);   // 512 x 8
        k1_stats<<<grid, 256>>>(pred);
    }
    k2_select1<<<BB * CC, 256>>>();
    {
        dim3 grid(NN / (256 * 16), BB);  // 128 x 8
        k5_reduce<<<grid, 256>>>(out);
    }
}

// round 5
// speedup vs baseline: 2.2579x; 1.0056x over previous
#include <cuda_runtime.h>
#include <math.h>

#define BB 8
#define CC 19
#define NN (512*1024)
#define BN (BB*NN)
#define NB12 10752            // 20-bit prefix buckets: (u>>12) - BASE12
#define BASE12 0x3D000
#define CH12 (NB12/256)       // 42 buckets per thread in k2
#define K5_BLOCKS (NN/(256*16)*BB)   // 128 x 8 = 1024

// ---------------- static scratch (zero-initialized at module load; every
// kernel leaves its state zeroed for the next graph replay) ----------------
__device__ __align__(16) unsigned g_key[BN];            // 16 MB
__device__ __align__(16) int      g_hist1[BB*CC*NB12];  // 6.5 MB
__device__ unsigned       g_thr[BB*CC];
__device__ int            g_need[BB*CC];
__device__ int            g_claim[BB*CC];
__device__ double         g_sum;
__device__ unsigned long long g_cnt;
__device__ unsigned       g_done;

// ---------------- K1: softmax stats, 2 pixels/thread, 4 CTAs/SM ----------------
__global__ __launch_bounds__(256, 4) void k1_stats(const float* __restrict__ pred) {
    int t = blockIdx.x * blockDim.x + threadIdx.x;   // float2 index within image
    int b = blockIdx.y;
    const float2* p = (const float2*)(pred + (size_t)b * CC * NN) + t;
    const int cs = NN / 2;

    // front-batch all 19 loads; evict-first so g_key stays resident in L2
    float2 r[CC];
#pragma unroll
    for (int c = 0; c < CC; c++) r[c] = __ldcs(&p[c * cs]);

    unsigned uo[2];
#define PROC(J, FIELD) { \
    float m = r[0].FIELD; \
    _Pragma("unroll") \
    for (int c = 1; c < CC; c++) m = fmaxf(m, r[c].FIELD); \
    int lab = 0; \
    float s = 0.0f; \
    _Pragma("unroll") \
    for (int c = CC - 1; c >= 0; c--) { \
        float x = r[c].FIELD; \
        s += __expf(x - m); \
        if (x == m) lab = c;                 /* first occurrence wins */ \
    } \
    float prob = __fdividef(1.0f, s); \
    unsigned u = __float_as_uint(prob); \
    uo[J] = (u & ~31u) | (unsigned)lab; \
    int key1 = min((int)(u >> 12) - BASE12, NB12 - 1); \
    key1 = max(key1, 0); \
    atomicAdd(&g_hist1[(b * CC + lab) * NB12 + key1], 1); }

    PROC(0, x) PROC(1, y)
#undef PROC

    uint2 out; out.x = uo[0]; out.y = uo[1];
    ((uint2*)g_key)[b * cs + t] = out;
}

// ---------------- K2: per-(image,class) threshold select (152 blocks);
//                  re-zeroes its histogram slice after reading ----------------
__global__ __launch_bounds__(256) void k2_select1() {
    int bc = blockIdx.x;
    int* h = &g_hist1[bc * NB12];
    int t0 = threadIdx.x * CH12;

    int hv[CH12];
    int s = 0;
#pragma unroll 6
    for (int j = 0; j < CH12; j++) { hv[j] = h[t0 + j]; s += hv[j]; }
#pragma unroll 6
    for (int j = 0; j < CH12; j++) h[t0 + j] = 0;

    __shared__ int sa[256], sb[256];
    sa[threadIdx.x] = s;
    __syncthreads();
    int* src = sa; int* dst = sb;
    for (int d = 1; d < 256; d <<= 1) {
        int v = src[threadIdx.x] + ((threadIdx.x + d < 256) ? src[threadIdx.x + d] : 0);
        dst[threadIdx.x] = v;
        __syncthreads();
        int* tp = src; src = dst; dst = tp;
    }

    int total = src[0];
    int k = (int)((float)total * 0.66f);   // fp32 truncation matches reference
    int above = (threadIdx.x + 1 < 256) ? src[threadIdx.x + 1] : 0;

    __shared__ int s_b1, s_need;
    if (threadIdx.x == 0) { s_b1 = -1; s_need = 0; }
    __syncthreads();

    if (k > 0 && above < k && above + s >= k) {
        int cum = above;
        for (int j = CH12 - 1; j >= 0; j--) {
            int hj = hv[j];
            if (cum < k && cum + hj >= k) { s_b1 = t0 + j; s_need = k - cum; }
            cum += hj;
        }
    }
    __syncthreads();
    if (threadIdx.x == 0) {
        g_thr[bc]  = (s_b1 >= 0) ? (unsigned)(BASE12 + s_b1) : 0xFFFFFFFFu;
        g_need[bc] = s_need;
    }
}

// ---------------- K5: selection + reduction (4x uint4 per thread) + fused
//                  finalize via last-block ticket; resets accumulators ----------------
__global__ __launch_bounds__(256) void k5_reduce(float* __restrict__ out) {
    __shared__ unsigned sthr[CC];
    int b = blockIdx.y;
    if (threadIdx.x < CC) sthr[threadIdx.x] = g_thr[b * CC + threadIdx.x];
    __syncthreads();

    int t = blockIdx.x * blockDim.x + threadIdx.x;
    const uint4* kp = (const uint4*)g_key + b * (NN / 4);
    const int q = NN / 16;   // quarter, in uint4 units
    uint4 v0 = kp[t];
    uint4 v1 = kp[t + q];
    uint4 v2 = kp[t + 2 * q];
    uint4 v3 = kp[t + 3 * q];
    unsigned u[16] = { v0.x, v0.y, v0.z, v0.w, v1.x, v1.y, v1.z, v1.w,
                       v2.x, v2.y, v2.z, v2.w, v3.x, v3.y, v3.z, v3.w };

    float nll = 0.0f;
    int   cnt = 0;
#pragma unroll
    for (int j = 0; j < 16; j++) {
        int lab = (int)(u[j] & 31u);
        float prob = __uint_as_float(u[j] & ~31u);
        unsigned ph = u[j] >> 12;
        unsigned thr = sthr[lab];
        bool sel = (prob > 0.9f) || (ph > thr);
        if (!sel && ph == thr) {
            int bc = b * CC + lab;
            sel = (atomicAdd(&g_claim[bc], 1) < g_need[bc]);
        }
        if (sel) { nll += -__logf(prob); cnt++; }
    }

#pragma unroll
    for (int o = 16; o > 0; o >>= 1) {
        nll += __shfl_xor_sync(0xFFFFFFFFu, nll, o);
        cnt += __shfl_xor_sync(0xFFFFFFFFu, cnt, o);
    }
    __shared__ float ws[8];
    __shared__ int   wc[8];
    int wid = threadIdx.x >> 5, lid = threadIdx.x & 31;
    if (lid == 0) { ws[wid] = nll; wc[wid] = cnt; }
    __syncthreads();
    if (threadIdx.x == 0) {
        float s = 0.0f; int c = 0;
#pragma unroll
        for (int w = 0; w < 8; w++) { s += ws[w]; c += wc[w]; }
        if (c > 0) {
            atomicAdd(&g_sum, (double)s);
            atomicAdd(&g_cnt, (unsigned long long)c);
        }
        __threadfence();
        unsigned ticket = atomicAdd(&g_done, 1);
        if (ticket == K5_BLOCKS - 1) {
            double             fs = atomicAdd(&g_sum, 0.0);
            unsigned long long fc = atomicAdd(&g_cnt, 0ull);
            if (fc == 0) fc = 1;
            out[0] = (float)(fs / (double)fc);
            g_sum = 0.0; g_cnt = 0ull; g_done = 0u;
            for (int i = 0; i < BB * CC; i++) g_claim[i] = 0;
        }
    }
}

// ---------------- launch ----------------
extern "C" void kernel_launch(void* const* d_in, const int* in_sizes, int n_in,
                              void* d_out, int out_size) {
    const float* pred = (const float*)d_in[0];
    float* out = (float*)d_out;

    {
        dim3 grid(NN / (256 * 2), BB);   // 1024 x 8
        k1_stats<<<grid, 256>>>(pred);
    }
    k2_select1<<<BB * CC, 256>>>();
    {
        dim3 grid(NN / (256 * 16), BB);  // 128 x 8
        k5_reduce<<<grid, 256>>>(out);
    }
}

// round 7
// speedup vs baseline: 2.4914x; 1.1034x over previous
#include <cuda_runtime.h>
#include <math.h>

#define BB 8
#define CC 19
#define NN (512*1024)
#define NBS 8704              // s-bit buckets: (bits(s)>>12) - BASES ; s in [1,19]
#define BASES 0x3F800
#define CHS 34                // buckets per thread in k2 (256*34 = 8704)
#define JB09 227              // bucket containing s = 1/0.9f
#define JB09_T 6              // owning thread (227/34)
#define JB09_L 23             // local index (227 - 6*34)
#define FRAC09 0.5556         // fraction of bucket 227 with s < 1/0.9 (conf side)
#define NLL_SCALE 4194304.0f  // 2^22 fixed-point for nll
#define K2_BLOCKS (BB*CC)

// ---------------- static scratch (zero at load; self-cleaning per replay) ----
__device__ __align__(16) unsigned long long g_hist[BB*CC*NBS];  // 10.6 MB
__device__ double             g_sum;
__device__ unsigned long long g_cnt;
__device__ unsigned           g_done;

// ---------------- K1: softmax stats -> packed (count|nll) histogram ----------
__global__ __launch_bounds__(256, 4) void k1_stats(const float* __restrict__ pred) {
    int t = blockIdx.x * blockDim.x + threadIdx.x;   // float2 index within image
    int b = blockIdx.y;
    const float2* p = (const float2*)(pred + (size_t)b * CC * NN) + t;
    const int cs = NN / 2;

    float2 r[CC];
#pragma unroll
    for (int c = 0; c < CC; c++) r[c] = __ldcs(&p[c * cs]);

#define PROC(FIELD) { \
    float m = r[0].FIELD; \
    _Pragma("unroll") \
    for (int c = 1; c < CC; c++) m = fmaxf(m, r[c].FIELD); \
    int lab = 0; \
    float s = 0.0f; \
    _Pragma("unroll") \
    for (int c = CC - 1; c >= 0; c--) { \
        float x = r[c].FIELD; \
        s += __expf(x - m); \
        if (x == m) lab = c;              /* first occurrence wins */ \
    } \
    float nll = __logf(s);                /* -log(max_prob), in [0, log 19] */ \
    unsigned us = __float_as_uint(s); \
    int key = min(max((int)(us >> 12) - BASES, 0), NBS - 1); \
    unsigned long long contrib = (1ull << 44) \
        | (unsigned long long)(unsigned)(nll * NLL_SCALE); \
    atomicAdd(&g_hist[((size_t)(b * CC + lab)) * NBS + key], contrib); }

    PROC(x) PROC(y)
#undef PROC
}

// ---------------- K2: per-(image,class) select + loss, fused finalize --------
// Bucket order: ascending s == DESCENDING prob. Top-k = lowest buckets.
// Case analysis (thr = rank-k crossing bucket):
//   thr > JB09 : conf set (prob>0.9, buckets <227ish) is a SUBSET of top-k
//                -> selection = exactly top-k.
//   thr < JB09 : top-k is a subset of the conf set -> selection = conf set.
//   thr == JB09: union inside the bucket = max(need, frac*count) from low end.
__global__ __launch_bounds__(256) void k2_select(float* __restrict__ out) {
    const unsigned long long MASK44 = (1ull << 44) - 1ull;
    int bc = blockIdx.x;
    unsigned long long* h = &g_hist[(size_t)bc * NBS];
    int tid = threadIdx.x;
    int t0 = tid * CHS;

    // phase A: chunk sum (packed add is safe: fields can't overflow)
    unsigned long long chunk = 0ull;
#pragma unroll 2
    for (int j = 0; j < CHS; j++) chunk += h[t0 + j];

    // inclusive prefix scan of packed chunk sums
    __shared__ unsigned long long sa[256], sb[256];
    sa[tid] = chunk;
    __syncthreads();
    unsigned long long* src = sa; unsigned long long* dst = sb;
    for (int d = 1; d < 256; d <<= 1) {
        dst[tid] = src[tid] + ((tid >= d) ? src[tid - d] : 0ull);
        __syncthreads();
        unsigned long long* tp = src; src = dst; dst = tp;
    }
    unsigned long long pre_pack = (tid > 0) ? src[tid - 1] : 0ull;
    long long total = (long long)(src[255] >> 44);
    long long k = (long long)(int)((float)total * 0.66f);  // fp32 trunc = reference

    __shared__ long long s_need, s_thrcnt, s_pcnt09, s_c09cnt;
    __shared__ unsigned long long s_ltnll, s_thrnll, s_pnll09, s_c09nll;
    __shared__ int s_thr;
    if (tid == 0) { s_thr = NBS; s_need = 0; s_thrcnt = 1; s_thrnll = 0; s_ltnll = 0; }
    __syncthreads();

    // phase B1: thread owning the rank-k crossing walks its chunk (L2-hot re-read)
    long long pre_cnt = (long long)(pre_pack >> 44);
    long long ccnt    = (long long)(chunk >> 44);
    if (k > 0 && pre_cnt < k && pre_cnt + ccnt >= k) {
        long long cum = pre_cnt;
        unsigned long long ltn = pre_pack & MASK44;
        for (int j = 0; j < CHS; j++) {
            unsigned long long v = h[t0 + j];
            long long c = (long long)(v >> 44);
            unsigned long long n = v & MASK44;
            if (cum < k && cum + c >= k) {
                s_thr = t0 + j; s_need = k - cum;
                s_thrcnt = (c > 0) ? c : 1; s_thrnll = n; s_ltnll = ltn;
                break;
            }
            ltn += n; cum += c;
        }
    }
    // phase B2: thread owning the 0.9-confidence bucket gathers conf-set stats
    if (tid == JB09_T) {
        long long pc = pre_cnt;
        unsigned long long pn = pre_pack & MASK44;
        unsigned long long v09 = 0ull;
        for (int j = 0; j < CHS; j++) {
            unsigned long long v = h[t0 + j];
            if (j < JB09_L) { pc += (long long)(v >> 44); pn += v & MASK44; }
            if (j == JB09_L) v09 = v;
        }
        s_pcnt09 = pc; s_pnll09 = pn;
        s_c09cnt = (long long)(v09 >> 44); s_c09nll = v09 & MASK44;
    }
    __syncthreads();

    // phase C: zero the histogram slice for the next replay
#pragma unroll 2
    for (int j = 0; j < CHS; j++) h[t0 + j] = 0ull;

    if (tid == 0) {
        const double INV = 1.0 / (double)NLL_SCALE;
        long long cnt_sel = 0; double sum_sel = 0.0;
        if (k > 0 && s_thr > JB09) {
            // threshold prob < 0.9: conf set inside top-k -> selection = top-k
            double avg = (double)s_thrnll * INV / (double)s_thrcnt;
            cnt_sel = k;
            sum_sel = (double)s_ltnll * INV + (double)s_need * avg;
        } else if (k > 0 && s_thr == JB09) {
            // tie bucket straddles 0.9: union inside bucket from the low-s end
            double avg = (double)s_thrnll * INV / (double)s_thrcnt;
            double cA = FRAC09 * (double)s_thrcnt;
            double selt = fmax((double)s_need, cA);
            cnt_sel = (k - s_need) + (long long)(selt + 0.5);
            sum_sel = (double)s_ltnll * INV + selt * avg;
        } else {
            // k==0, or threshold prob > 0.9 (top-k inside conf set) -> conf set
            double cA = FRAC09 * (double)s_c09cnt;
            cnt_sel = s_pcnt09 + (long long)(cA + 0.5);
            sum_sel = ((double)s_pnll09 + FRAC09 * (double)s_c09nll) * INV;
        }
        if (cnt_sel > 0) {
            atomicAdd(&g_sum, sum_sel);
            atomicAdd(&g_cnt, (unsigned long long)cnt_sel);
        }
        __threadfence();
        unsigned ticket = atomicAdd(&g_done, 1);
        if (ticket == K2_BLOCKS - 1) {
            double             fs = atomicAdd(&g_sum, 0.0);
            unsigned long long fc = atomicAdd(&g_cnt, 0ull);
            if (fc == 0) fc = 1;
            out[0] = (float)(fs / (double)fc);
            g_sum = 0.0; g_cnt = 0ull; g_done = 0u;
        }
    }
}

// ---------------- launch ----------------
extern "C" void kernel_launch(void* const* d_in, const int* in_sizes, int n_in,
                              void* d_out, int out_size) {
    const float* pred = (const float*)d_in[0];
    float* out = (float*)d_out;

    {
        dim3 grid(NN / (256 * 2), BB);   // 1024 x 8
        k1_stats<<<grid, 256>>>(pred);
    }
    k2_select<<<K2_BLOCKS, 256>>>(out);
}

// round 8
// speedup vs baseline: 2.6370x; 1.0585x over previous
#include <cuda_runtime.h>
#include <math.h>

#define BB 8
#define CC 19
#define NN (512*1024)
#define NBS 9216              // s-bit buckets (padded to 1024*9): (bits(s)>>12)-BASES
#define NBS_USED 8704         // buckets actually reachable for s in [1,19]
#define BASES 0x3F800
#define K2T 1024              // k2 threads per block
#define CHS 9                 // buckets per thread in k2 (1024*9 = 9216)
#define JB09 227              // bucket containing s = 1/0.9f
#define JB09_T 25             // owning thread (227/9)
#define JB09_L 2              // local index (227 - 25*9)
#define FRAC09 0.5556         // fraction of bucket 227 with s < 1/0.9 (conf side)
#define NLL_SCALE 4194304.0f  // 2^22 fixed-point for nll
#define K2_BLOCKS (BB*CC)

// ---------------- static scratch (zero at load; self-cleaning per replay) ----
__device__ __align__(16) unsigned long long g_hist[BB*CC*NBS];  // 11.2 MB
__device__ double             g_sum;
__device__ unsigned long long g_cnt;
__device__ unsigned           g_done;

// ---------------- K1: softmax stats -> packed (count|nll) histogram ----------
__global__ __launch_bounds__(256, 4) void k1_stats(const float* __restrict__ pred) {
    int t = blockIdx.x * blockDim.x + threadIdx.x;   // float2 index within image
    int b = blockIdx.y;
    const float2* p = (const float2*)(pred + (size_t)b * CC * NN) + t;
    const int cs = NN / 2;

    float2 r[CC];
#pragma unroll
    for (int c = 0; c < CC; c++) r[c] = __ldcs(&p[c * cs]);

#define PROC(FIELD) { \
    float m = r[0].FIELD; \
    _Pragma("unroll") \
    for (int c = 1; c < CC; c++) m = fmaxf(m, r[c].FIELD); \
    int lab = 0; \
    float s = 0.0f; \
    _Pragma("unroll") \
    for (int c = CC - 1; c >= 0; c--) { \
        float x = r[c].FIELD; \
        s += __expf(x - m); \
        if (x == m) lab = c;              /* first occurrence wins */ \
    } \
    float nll = __logf(s);                /* -log(max_prob), in [0, log 19] */ \
    unsigned us = __float_as_uint(s); \
    int key = min(max((int)(us >> 12) - BASES, 0), NBS_USED - 1); \
    unsigned long long contrib = (1ull << 44) \
        | (unsigned long long)(unsigned)(nll * NLL_SCALE); \
    atomicAdd(&g_hist[((size_t)(b * CC + lab)) * NBS + key], contrib); }

    PROC(x) PROC(y)
#undef PROC
}

// ---------------- K2: per-(image,class) select + loss, fused finalize --------
// Bucket order: ascending s == DESCENDING prob. Top-k = lowest buckets.
// Case analysis (thr = rank-k crossing bucket):
//   thr > JB09 : conf set (prob>0.9) is a subset of top-k -> selection = top-k.
//   thr < JB09 : top-k is a subset of the conf set -> selection = conf set.
//   thr == JB09: union inside the bucket = max(need, frac*count) from low end.
__global__ __launch_bounds__(K2T) void k2_select(float* __restrict__ out) {
    const unsigned long long MASK44 = (1ull << 44) - 1ull;
    int bc = blockIdx.x;
    unsigned long long* h = &g_hist[(size_t)bc * NBS];
    int tid = threadIdx.x;
    int t0 = tid * CHS;

    // phase A: chunk values -> registers (packed add safe: fields can't overflow)
    unsigned long long hv[CHS];
    unsigned long long chunk = 0ull;
#pragma unroll
    for (int j = 0; j < CHS; j++) { hv[j] = h[t0 + j]; chunk += hv[j]; }
    // zero global slice immediately (registers keep the values)
#pragma unroll
    for (int j = 0; j < CHS; j++) h[t0 + j] = 0ull;

    // inclusive prefix scan of packed chunk sums (1024 wide, 10 steps)
    __shared__ unsigned long long sa[K2T], sb[K2T];
    sa[tid] = chunk;
    __syncthreads();
    unsigned long long* src = sa; unsigned long long* dst = sb;
    for (int d = 1; d < K2T; d <<= 1) {
        dst[tid] = src[tid] + ((tid >= d) ? src[tid - d] : 0ull);
        __syncthreads();
        unsigned long long* tp = src; src = dst; dst = tp;
    }
    unsigned long long pre_pack = (tid > 0) ? src[tid - 1] : 0ull;
    long long total = (long long)(src[K2T - 1] >> 44);
    long long k = (long long)(int)((float)total * 0.66f);  // fp32 trunc = reference

    __shared__ long long s_need, s_thrcnt, s_pcnt09, s_c09cnt;
    __shared__ unsigned long long s_ltnll, s_thrnll, s_pnll09, s_c09nll;
    __shared__ int s_thr;
    if (tid == 0) { s_thr = NBS; s_need = 0; s_thrcnt = 1; s_thrnll = 0; s_ltnll = 0; }
    __syncthreads();

    // phase B1: thread owning the rank-k crossing walks its registers
    long long pre_cnt = (long long)(pre_pack >> 44);
    long long ccnt    = (long long)(chunk >> 44);
    if (k > 0 && pre_cnt < k && pre_cnt + ccnt >= k) {
        long long cum = pre_cnt;
        unsigned long long ltn = pre_pack & MASK44;
#pragma unroll
        for (int j = 0; j < CHS; j++) {
            unsigned long long v = hv[j];
            long long c = (long long)(v >> 44);
            unsigned long long n = v & MASK44;
            if (cum < k && cum + c >= k) {
                s_thr = t0 + j; s_need = k - cum;
                s_thrcnt = (c > 0) ? c : 1; s_thrnll = n; s_ltnll = ltn;
                break;
            }
            ltn += n; cum += c;
        }
    }
    // phase B2: thread owning the 0.9-confidence bucket gathers conf-set stats
    if (tid == JB09_T) {
        long long pc = pre_cnt;
        unsigned long long pn = pre_pack & MASK44;
#pragma unroll
        for (int j = 0; j < JB09_L; j++) {
            pc += (long long)(hv[j] >> 44); pn += hv[j] & MASK44;
        }
        unsigned long long v09 = hv[JB09_L];
        s_pcnt09 = pc; s_pnll09 = pn;
        s_c09cnt = (long long)(v09 >> 44); s_c09nll = v09 & MASK44;
    }
    __syncthreads();

    if (tid == 0) {
        const double INV = 1.0 / (double)NLL_SCALE;
        long long cnt_sel = 0; double sum_sel = 0.0;
        if (k > 0 && s_thr > JB09) {
            // threshold prob < 0.9: conf set inside top-k -> selection = top-k
            double avg = (double)s_thrnll * INV / (double)s_thrcnt;
            cnt_sel = k;
            sum_sel = (double)s_ltnll * INV + (double)s_need * avg;
        } else if (k > 0 && s_thr == JB09) {
            // tie bucket straddles 0.9: union inside bucket from the low-s end
            double avg = (double)s_thrnll * INV / (double)s_thrcnt;
            double cA = FRAC09 * (double)s_thrcnt;
            double selt = fmax((double)s_need, cA);
            cnt_sel = (k - s_need) + (long long)(selt + 0.5);
            sum_sel = (double)s_ltnll * INV + selt * avg;
        } else {
            // k==0, or threshold prob > 0.9 (top-k inside conf set) -> conf set
            double cA = FRAC09 * (double)s_c09cnt;
            cnt_sel = s_pcnt09 + (long long)(cA + 0.5);
            sum_sel = ((double)s_pnll09 + FRAC09 * (double)s_c09nll) * INV;
        }
        if (cnt_sel > 0) {
            atomicAdd(&g_sum, sum_sel);
            atomicAdd(&g_cnt, (unsigned long long)cnt_sel);
        }
        __threadfence();
        unsigned ticket = atomicAdd(&g_done, 1);
        if (ticket == K2_BLOCKS - 1) {
            double             fs = atomicAdd(&g_sum, 0.0);
            unsigned long long fc = atomicAdd(&g_cnt, 0ull);
            if (fc == 0) fc = 1;
            out[0] = (float)(fs / (double)fc);
            g_sum = 0.0; g_cnt = 0ull; g_done = 0u;
        }
    }
}

// ---------------- launch ----------------
extern "C" void kernel_launch(void* const* d_in, const int* in_sizes, int n_in,
                              void* d_out, int out_size) {
    const float* pred = (const float*)d_in[0];
    float* out = (float*)d_out;

    {
        dim3 grid(NN / (256 * 2), BB);   // 1024 x 8
        k1_stats<<<grid, 256>>>(pred);
    }
    k2_select<<<K2_BLOCKS, K2T>>>(out);
}

// round 9
// speedup vs baseline: 2.6395x; 1.0009x over previous
#include <cuda_runtime.h>
#include <math.h>

#define BB 8
#define CC 19
#define NN (512*1024)
#define NBS 9216              // s-bit buckets (padded to 1024*9): (bits(s)>>12)-BASES
#define NBS_USED 8704         // buckets actually reachable for s in [1,19]
#define BASES 0x3F800
#define K2T 1024              // k2 threads per block
#define CHS 9                 // buckets per thread in k2 (1024*9 = 9216)
#define JB09 227              // bucket containing s = 1/0.9f
#define JB09_T 25             // owning thread (227/9)
#define JB09_L 2              // local index (227 - 25*9)
#define FRAC09 0.5556         // fraction of bucket 227 with s < 1/0.9 (conf side)
#define NLL_SCALE 4194304.0f  // 2^22 fixed-point for nll
#define K2_BLOCKS (BB*CC)

// ---------------- static scratch (zero at load; self-cleaning per replay) ----
__device__ __align__(16) unsigned long long g_hist[BB*CC*NBS];  // 11.2 MB
__device__ double             g_sum;
__device__ unsigned long long g_cnt;
__device__ unsigned           g_done;

// ---------------- K1: softmax stats -> packed (count|nll) histogram ----------
__global__ __launch_bounds__(256, 4) void k1_stats(const float* __restrict__ pred) {
    int t = blockIdx.x * blockDim.x + threadIdx.x;   // float2 index within image
    int b = blockIdx.y;
    const float2* p = (const float2*)(pred + (size_t)b * CC * NN) + t;
    const int cs = NN / 2;

    float2 r[CC];
#pragma unroll
    for (int c = 0; c < CC; c++) r[c] = __ldcs(&p[c * cs]);

#define PROC(FIELD) { \
    float m = r[0].FIELD; \
    _Pragma("unroll") \
    for (int c = 1; c < CC; c++) m = fmaxf(m, r[c].FIELD); \
    int lab = 0; \
    float s = 0.0f; \
    _Pragma("unroll") \
    for (int c = CC - 1; c >= 0; c--) { \
        float x = r[c].FIELD; \
        s += __expf(x - m); \
        if (x == m) lab = c;              /* first occurrence wins */ \
    } \
    float nll = __logf(s);                /* -log(max_prob), in [0, log 19] */ \
    unsigned us = __float_as_uint(s); \
    int key = min(max((int)(us >> 12) - BASES, 0), NBS_USED - 1); \
    unsigned long long contrib = (1ull << 44) \
        | (unsigned long long)(unsigned)(nll * NLL_SCALE); \
    atomicAdd(&g_hist[((size_t)(b * CC + lab)) * NBS + key], contrib); }

    PROC(x) PROC(y)
#undef PROC
}

// ---------------- K2: per-(image,class) select + loss, fused finalize --------
// Bucket order: ascending s == DESCENDING prob. Top-k = lowest buckets.
// Case analysis (thr = rank-k crossing bucket):
//   thr > JB09 : conf set (prob>0.9) is a subset of top-k -> selection = top-k.
//   thr < JB09 : top-k is a subset of the conf set -> selection = conf set.
//   thr == JB09: union inside the bucket = max(need, frac*count) from low end.
__global__ __launch_bounds__(K2T) void k2_select(float* __restrict__ out) {
    const unsigned long long MASK44 = (1ull << 44) - 1ull;
    int bc = blockIdx.x;
    unsigned long long* h = &g_hist[(size_t)bc * NBS];
    int tid = threadIdx.x;
    int lane = tid & 31, wid = tid >> 5;
    int t0 = tid * CHS;

    // phase A: chunk values -> registers (packed add safe: fields can't overflow)
    unsigned long long hv[CHS];
    unsigned long long chunk = 0ull;
#pragma unroll
    for (int j = 0; j < CHS; j++) { hv[j] = h[t0 + j]; chunk += hv[j]; }
    // zero global slice immediately (registers keep the values)
#pragma unroll
    for (int j = 0; j < CHS; j++) h[t0 + j] = 0ull;

    // hierarchical scan: warp-inclusive via shfl (no barriers), then warp totals
    unsigned long long inc = chunk;
#pragma unroll
    for (int d = 1; d < 32; d <<= 1) {
        unsigned long long n = __shfl_up_sync(0xFFFFFFFFu, inc, d);
        if (lane >= d) inc += n;
    }
    __shared__ unsigned long long wtot[32];
    if (lane == 31) wtot[wid] = inc;
    __syncthreads();
    if (wid == 0) {
        unsigned long long w = wtot[lane];
#pragma unroll
        for (int d = 1; d < 32; d <<= 1) {
            unsigned long long n = __shfl_up_sync(0xFFFFFFFFu, w, d);
            if (lane >= d) w += n;
        }
        wtot[lane] = w;   // inclusive warp prefix
    }
    __syncthreads();
    unsigned long long warp_excl = (wid > 0) ? wtot[wid - 1] : 0ull;
    unsigned long long pre_pack = warp_excl + (inc - chunk);  // exclusive thread prefix
    long long total = (long long)(wtot[31] >> 44);
    long long k = (long long)(int)((float)total * 0.66f);  // fp32 trunc = reference

    __shared__ long long s_need, s_thrcnt, s_pcnt09, s_c09cnt;
    __shared__ unsigned long long s_ltnll, s_thrnll, s_pnll09, s_c09nll;
    __shared__ int s_thr;
    if (tid == 0) { s_thr = NBS; s_need = 0; s_thrcnt = 1; s_thrnll = 0; s_ltnll = 0; }
    __syncthreads();

    // phase B1: thread owning the rank-k crossing walks its registers
    long long pre_cnt = (long long)(pre_pack >> 44);
    long long ccnt    = (long long)(chunk >> 44);
    if (k > 0 && pre_cnt < k && pre_cnt + ccnt >= k) {
        long long cum = pre_cnt;
        unsigned long long ltn = pre_pack & MASK44;
#pragma unroll
        for (int j = 0; j < CHS; j++) {
            unsigned long long v = hv[j];
            long long c = (long long)(v >> 44);
            unsigned long long n = v & MASK44;
            if (cum < k && cum + c >= k) {
                s_thr = t0 + j; s_need = k - cum;
                s_thrcnt = (c > 0) ? c : 1; s_thrnll = n; s_ltnll = ltn;
                break;
            }
            ltn += n; cum += c;
        }
    }
    // phase B2: thread owning the 0.9-confidence bucket gathers conf-set stats
    if (tid == JB09_T) {
        long long pc = pre_cnt;
        unsigned long long pn = pre_pack & MASK44;
#pragma unroll
        for (int j = 0; j < JB09_L; j++) {
            pc += (long long)(hv[j] >> 44); pn += hv[j] & MASK44;
        }
        unsigned long long v09 = hv[JB09_L];
        s_pcnt09 = pc; s_pnll09 = pn;
        s_c09cnt = (long long)(v09 >> 44); s_c09nll = v09 & MASK44;
    }
    __syncthreads();

    if (tid == 0) {
        const double INV = 1.0 / (double)NLL_SCALE;
        long long cnt_sel = 0; double sum_sel = 0.0;
        if (k > 0 && s_thr > JB09) {
            // threshold prob < 0.9: conf set inside top-k -> selection = top-k
            double avg = (double)s_thrnll * INV / (double)s_thrcnt;
            cnt_sel = k;
            sum_sel = (double)s_ltnll * INV + (double)s_need * avg;
        } else if (k > 0 && s_thr == JB09) {
            // tie bucket straddles 0.9: union inside bucket from the low-s end
            double avg = (double)s_thrnll * INV / (double)s_thrcnt;
            double cA = FRAC09 * (double)s_thrcnt;
            double selt = fmax((double)s_need, cA);
            cnt_sel = (k - s_need) + (long long)(selt + 0.5);
            sum_sel = (double)s_ltnll * INV + selt * avg;
        } else {
            // k==0, or threshold prob > 0.9 (top-k inside conf set) -> conf set
            double cA = FRAC09 * (double)s_c09cnt;
            cnt_sel = s_pcnt09 + (long long)(cA + 0.5);
            sum_sel = ((double)s_pnll09 + FRAC09 * (double)s_c09nll) * INV;
        }
        if (cnt_sel > 0) {
            atomicAdd(&g_sum, sum_sel);
            atomicAdd(&g_cnt, (unsigned long long)cnt_sel);
        }
        __threadfence();
        unsigned ticket = atomicAdd(&g_done, 1);
        if (ticket == K2_BLOCKS - 1) {
            double             fs = atomicAdd(&g_sum, 0.0);
            unsigned long long fc = atomicAdd(&g_cnt, 0ull);
            if (fc == 0) fc = 1;
            out[0] = (float)(fs / (double)fc);
            g_sum = 0.0; g_cnt = 0ull; g_done = 0u;
        }
    }
}

// ---------------- launch ----------------
extern "C" void kernel_launch(void* const* d_in, const int* in_sizes, int n_in,
                              void* d_out, int out_size) {
    const float* pred = (const float*)d_in[0];
    float* out = (float*)d_out;

    {
        dim3 grid(NN / (256 * 2), BB);   // 1024 x 8
        k1_stats<<<grid, 256>>>(pred);
    }
    k2_select<<<K2_BLOCKS, K2T>>>(out);
}